// round 6
// baseline (speedup 1.0000x reference)
#include <cuda_runtime.h>
#include <math.h>
#include <float.h>

// Problem dims
#define E_N      256
#define C_N      128
#define HW       3136          // 56*56
#define NC       200
#define NP       512
#define NL       64
#define LL       8
#define EDGE_DIM 256           // 2*C
#define LOOP_IN  258
#define FEAT     64

// Output layout (concatenated tuple, float32):
//   [0, 32768)        out [E, C]
//   [32768, 33024)    edge_conf [E]
//   [33024, 33088)    loop_conf [NL]
//   [33088, 49472)    loop_edges [NL, E]
#define OUT_FULL_SIZE 49472

// ---------------- device scratch (no allocations allowed) ----------------
__device__ float g_edge_x[E_N * EDGE_DIM];        // pooled img feats | coord feats
__device__ float g_corner_feat[NC * EDGE_DIM];
__device__ float g_loop_feat[NL * FEAT];
__device__ float g_loop_conf[NL];
__device__ float g_coord_feat[E_N * FEAT];
// transposed weights (coalesced inner-loop access: lane = out-channel)
__device__ float g_Wep1T[EDGE_DIM * 64];          // [j][h]
__device__ float g_WaggT[192 * C_N];              // [j][c]
__device__ float g_Wc0T[LOOP_IN * 3 * 64];        // [(ic*3+k)][oc]
__device__ float g_Wc1T[64 * 3 * 64];
__device__ float g_Wc2T[64 * 3 * 64];

// ---------------- prep: weight transposes + coord half of edge_x ----------
__global__ void prep_kernel(const float* __restrict__ W_ep1,
                            const float* __restrict__ W_agg,
                            const float* __restrict__ Wc0,
                            const float* __restrict__ Wc1,
                            const float* __restrict__ Wc2,
                            const float* __restrict__ coord_x) {
    int tid = blockIdx.x * blockDim.x + threadIdx.x;
    int stride = gridDim.x * blockDim.x;
    for (int i = tid; i < EDGE_DIM * 64; i += stride) {
        int j = i >> 6, h = i & 63;
        g_Wep1T[i] = W_ep1[h * EDGE_DIM + j];
    }
    for (int i = tid; i < 192 * C_N; i += stride) {
        int j = i / C_N, c = i % C_N;
        g_WaggT[i] = W_agg[c * 192 + j];
    }
    for (int i = tid; i < LOOP_IN * 3 * 64; i += stride) {
        int ick = i >> 6, oc = i & 63;
        g_Wc0T[i] = Wc0[oc * (LOOP_IN * 3) + ick];
    }
    for (int i = tid; i < 64 * 3 * 64; i += stride) {
        int ick = i >> 6, oc = i & 63;
        g_Wc1T[i] = Wc1[oc * 192 + ick];
        g_Wc2T[i] = Wc2[oc * 192 + ick];
    }
    for (int i = tid; i < E_N * C_N; i += stride) {
        int e = i / C_N, c = i % C_N;
        g_edge_x[e * EDGE_DIM + C_N + c] = coord_x[i];
    }
}

// ---------------- global max pool: warp per (e,c) row --------------------
__global__ void __launch_bounds__(128, 16) pool_kernel(const float* __restrict__ image_x) {
    int gwarp = (blockIdx.x * blockDim.x + threadIdx.x) >> 5;   // 0..32767
    int lane = threadIdx.x & 31;
    const float4* row = (const float4*)(image_x + (size_t)gwarp * HW);
    float m = -FLT_MAX;
    // 784 float4 per row; 24 full rounds of 32 + tail of 16
    #pragma unroll 8
    for (int i = lane; i < 768; i += 32) {
        float4 v = row[i];
        m = fmaxf(m, fmaxf(fmaxf(v.x, v.y), fmaxf(v.z, v.w)));
    }
    if (lane < 16) {
        float4 v = row[768 + lane];
        m = fmaxf(m, fmaxf(fmaxf(v.x, v.y), fmaxf(v.z, v.w)));
    }
    #pragma unroll
    for (int o = 16; o; o >>= 1) m = fmaxf(m, __shfl_xor_sync(0xFFFFFFFFu, m, o));
    if (lane == 0) {
        int e = gwarp / C_N, c = gwarp % C_N;
        g_edge_x[e * EDGE_DIM + c] = m;
    }
}

// ---------------- edge confidence MLP: block per edge --------------------
__global__ void edgeconf_kernel(const float* __restrict__ b_ep1,
                                const float* __restrict__ W_ep2,
                                const float* __restrict__ b_ep2,
                                float* out_conf) {          // nullable
    __shared__ float sx[EDGE_DIM];
    __shared__ float sh[64];
    int e = blockIdx.x, t = threadIdx.x;     // 64 threads
    for (int i = t; i < EDGE_DIM; i += 64) sx[i] = g_edge_x[e * EDGE_DIM + i];
    __syncthreads();
    float acc = b_ep1[t];
    #pragma unroll 8
    for (int j = 0; j < EDGE_DIM; j++) acc += g_Wep1T[j * 64 + t] * sx[j];
    sh[t] = fmaxf(acc, 0.f) * W_ep2[t];
    __syncthreads();
    if (t == 0) {
        float s = b_ep2[0];
        #pragma unroll 8
        for (int j = 0; j < 64; j++) s += sh[j];
        float conf = 1.f / (1.f + expf(-s));
        if (out_conf) out_conf[e] = conf;
    }
}

// ---------------- corner scatter-mean (gather form, no atomics) ----------
__global__ void cornerfeat_kernel(const int* __restrict__ pairs) {
    __shared__ int sc[NP];
    __shared__ int se[NP];
    int c = blockIdx.x, t = threadIdx.x;     // 256 threads = feature dim
    for (int p = t; p < NP; p += 256) { sc[p] = pairs[2 * p]; se[p] = pairs[2 * p + 1]; }
    __syncthreads();
    float acc = 0.f; int cnt = 0;
    for (int p = 0; p < NP; p++) {
        if (sc[p] == c) { acc += g_edge_x[se[p] * EDGE_DIM + t]; cnt++; }
    }
    g_corner_feat[c * EDGE_DIM + t] = acc / fmaxf((float)cnt, 1.f);
}

// ---------------- loop encoder: block per loop ---------------------------
// threads: 256 = 64 out-channels x 4 position-groups (2 positions each)
__global__ void loopenc_kernel(const int* __restrict__ loops,
                               const float* __restrict__ corners_xy,
                               const float* __restrict__ bc0,
                               const float* __restrict__ bc1,
                               const float* __restrict__ bc2,
                               const float* __restrict__ Wl1,
                               const float* __restrict__ bl1,
                               const float* __restrict__ Wl2,
                               const float* __restrict__ bl2,
                               float* out_loopconf) {       // nullable
    __shared__ float s_a[LOOP_IN * 10];   // padded length-10 rows
    __shared__ float s_b[64 * 10];
    __shared__ float s_c[64 * 10];
    __shared__ float s_red[4 * 64];
    __shared__ int   s_cid[LL];
    int nl = blockIdx.x, t = threadIdx.x;
    if (t < LL) s_cid[t] = loops[nl * LL + t];
    __syncthreads();
    // build padded input [258][10]: pos 0 = x[1], pos 1..8 = x[0..7], pos 9 = x[6]
    for (int i = t; i < LOOP_IN * LL; i += 256) {
        int l = i / LOOP_IN, ch = i % LOOP_IN;
        int cid = s_cid[l];
        float v = (ch < EDGE_DIM) ? g_corner_feat[cid * EDGE_DIM + ch]
                                  : corners_xy[cid * 2 + (ch - EDGE_DIM)];
        s_a[ch * 10 + l + 1] = v;
    }
    __syncthreads();
    for (int ch = t; ch < LOOP_IN; ch += 256) {
        s_a[ch * 10]     = s_a[ch * 10 + 2];
        s_a[ch * 10 + 9] = s_a[ch * 10 + 7];
    }
    __syncthreads();

    int oc = t & 63, grp = t >> 6;
    int l0 = grp * 2;

    // conv0: 258 -> 64
    float a0 = bc0[oc], a1 = a0;
    for (int ic = 0; ic < LOOP_IN; ic++) {
        const float* sr = s_a + ic * 10;
        #pragma unroll
        for (int k = 0; k < 3; k++) {
            float w = g_Wc0T[(ic * 3 + k) * 64 + oc];
            a0 += w * sr[l0 + k];
            a1 += w * sr[l0 + 1 + k];
        }
    }
    s_b[oc * 10 + l0 + 1] = fmaxf(a0, 0.f);
    s_b[oc * 10 + l0 + 2] = fmaxf(a1, 0.f);
    __syncthreads();
    if (t < 64) { s_b[t * 10] = s_b[t * 10 + 2]; s_b[t * 10 + 9] = s_b[t * 10 + 7]; }
    __syncthreads();

    // conv1: 64 -> 64
    a0 = bc1[oc]; a1 = a0;
    for (int ic = 0; ic < 64; ic++) {
        const float* sr = s_b + ic * 10;
        #pragma unroll
        for (int k = 0; k < 3; k++) {
            float w = g_Wc1T[(ic * 3 + k) * 64 + oc];
            a0 += w * sr[l0 + k];
            a1 += w * sr[l0 + 1 + k];
        }
    }
    s_c[oc * 10 + l0 + 1] = fmaxf(a0, 0.f);
    s_c[oc * 10 + l0 + 2] = fmaxf(a1, 0.f);
    __syncthreads();
    if (t < 64) { s_c[t * 10] = s_c[t * 10 + 2]; s_c[t * 10 + 9] = s_c[t * 10 + 7]; }
    __syncthreads();

    // conv2: 64 -> 64, fused with max over positions
    a0 = bc2[oc]; a1 = a0;
    for (int ic = 0; ic < 64; ic++) {
        const float* sr = s_c + ic * 10;
        #pragma unroll
        for (int k = 0; k < 3; k++) {
            float w = g_Wc2T[(ic * 3 + k) * 64 + oc];
            a0 += w * sr[l0 + k];
            a1 += w * sr[l0 + 1 + k];
        }
    }
    s_red[grp * 64 + oc] = fmaxf(fmaxf(a0, a1), 0.f);   // relu then partial max
    __syncthreads();
    if (t < 64) {
        float lf = fmaxf(fmaxf(s_red[t], s_red[64 + t]),
                         fmaxf(s_red[128 + t], s_red[192 + t]));
        g_loop_feat[nl * 64 + t] = lf;
        s_a[t] = lf;   // reuse s_a front as lf staging
    }
    __syncthreads();
    // loop confidence MLP: 64 -> 32 -> 1 (warp 0)
    if (t < 32) {
        float h = bl1[t];
        #pragma unroll 8
        for (int j = 0; j < 64; j++) h += Wl1[t * 64 + j] * s_a[j];
        float v = fmaxf(h, 0.f) * Wl2[t];
        #pragma unroll
        for (int o = 16; o; o >>= 1) v += __shfl_xor_sync(0xFFFFFFFFu, v, o);
        if (t == 0) {
            float conf = 1.f / (1.f + expf(-(v + bl2[0])));
            g_loop_conf[nl] = conf;
            if (out_loopconf) out_loopconf[nl] = conf;
        }
    }
}

// ---------------- loop-edge incidence + coord_features: block per edge ---
__global__ void loopedge_kernel(const int* __restrict__ edge_corner,
                                const int* __restrict__ loops,
                                float* out_le) {            // nullable
    __shared__ int   s_loops[NL * LL];
    __shared__ float s_lw[NL];
    int e = blockIdx.x, t = threadIdx.x;   // 64 threads
    for (int i = t; i < NL * LL; i += 64) s_loops[i] = loops[i];
    int a = edge_corner[2 * e], b = edge_corner[2 * e + 1];
    __syncthreads();
    {
        int nl = t;
        const int* c = s_loops + nl * LL;
        bool hit = false;
        #pragma unroll
        for (int l = 0; l < LL; l++) {
            int cl = c[l];
            int cp = c[(l + LL - 1) & 7];
            int cn = c[(l + 1) & 7];
            if (a == cl && (b == cp || b == cn)) hit = true;
        }
        float le = hit ? 1.f : 0.f;
        if (out_le) out_le[nl * E_N + e] = le;
        s_lw[nl] = le * g_loop_conf[nl];
    }
    __syncthreads();
    // t = feature index; loop_feat column read is coalesced across lanes
    float num = 0.f, den = 0.f;
    for (int nl = 0; nl < NL; nl++) {
        float w = s_lw[nl];
        den += w;
        num += w * g_loop_feat[nl * 64 + t];
    }
    g_coord_feat[e * 64 + t] = num / fmaxf(den, 1e-4f);
}

// ---------------- final 1x1 conv (no bias) + relu: block per edge --------
__global__ void final_kernel(const float* __restrict__ coord_x,
                             float* __restrict__ out) {
    __shared__ float sx[192];
    int e = blockIdx.x, t = threadIdx.x;   // 128 threads
    sx[t] = coord_x[e * C_N + t];
    if (t < 64) sx[C_N + t] = g_coord_feat[e * 64 + t];
    __syncthreads();
    float acc = 0.f;
    #pragma unroll 8
    for (int j = 0; j < 192; j++) acc += g_WaggT[j * C_N + t] * sx[j];
    out[e * C_N + t] = fmaxf(acc, 0.f);
}

// ---------------- launch ---------------------------------------------------
extern "C" void kernel_launch(void* const* d_in, const int* in_sizes, int n_in,
                              void* d_out, int out_size) {
    const float* image_x     = (const float*)d_in[0];
    const float* coord_x     = (const float*)d_in[1];
    const float* corners     = (const float*)d_in[2];
    const int*   cep         = (const int*)  d_in[3];
    const int*   edge_corner = (const int*)  d_in[4];
    const int*   loops       = (const int*)  d_in[5];
    const float* W_ep1 = (const float*)d_in[6];
    const float* b_ep1 = (const float*)d_in[7];
    const float* W_ep2 = (const float*)d_in[8];
    const float* b_ep2 = (const float*)d_in[9];
    const float* Wc0   = (const float*)d_in[10];
    const float* bc0   = (const float*)d_in[11];
    const float* Wc1   = (const float*)d_in[12];
    const float* bc1   = (const float*)d_in[13];
    const float* Wc2   = (const float*)d_in[14];
    const float* bc2   = (const float*)d_in[15];
    const float* Wl1   = (const float*)d_in[16];
    const float* bl1   = (const float*)d_in[17];
    const float* Wl2   = (const float*)d_in[18];
    const float* bl2   = (const float*)d_in[19];
    const float* W_agg = (const float*)d_in[20];

    float* out = (float*)d_out;
    float* p_econf = nullptr;
    float* p_lconf = nullptr;
    float* p_le    = nullptr;
    if (out_size >= OUT_FULL_SIZE) {
        p_econf = out + E_N * C_N;
        p_lconf = p_econf + E_N;
        p_le    = p_lconf + NL;
    }

    prep_kernel<<<64, 256>>>(W_ep1, W_agg, Wc0, Wc1, Wc2, coord_x);
    pool_kernel<<<8192, 128>>>(image_x);
    edgeconf_kernel<<<E_N, 64>>>(b_ep1, W_ep2, b_ep2, p_econf);
    cornerfeat_kernel<<<NC, 256>>>(cep);
    loopenc_kernel<<<NL, 256>>>(loops, corners, bc0, bc1, bc2,
                                Wl1, bl1, Wl2, bl2, p_lconf);
    loopedge_kernel<<<E_N, 64>>>(edge_corner, loops, p_le);
    final_kernel<<<E_N, 128>>>(coord_x, out);
}

// round 8
// speedup vs baseline: 1.3703x; 1.3703x over previous
#include <cuda_runtime.h>
#include <math.h>
#include <float.h>

// Problem dims
#define E_N      256
#define C_N      128
#define HW       3136          // 56*56
#define NC       200
#define NP       512
#define NL       64
#define LL       8
#define EDGE_DIM 256           // 2*C
#define LOOP_IN  258
#define FEAT     64

// Output layout (concatenated tuple, float32):
//   [0, 32768)        out [E, C]
//   [32768, 33024)    edge_conf [E]
//   [33024, 33088)    loop_conf [NL]
//   [33088, 49472)    loop_edges [NL, E]
#define OUT_FULL_SIZE 49472

// ---------------- device scratch (no allocations allowed) ----------------
__device__ float g_edge_x[E_N * EDGE_DIM];        // pooled img feats | coord feats
__device__ float g_corner_feat[NC * EDGE_DIM];
__device__ float g_loop_feat[NL * FEAT];
__device__ float g_loop_conf[NL];
__device__ float g_coord_feat[E_N * FEAT];
// transposed weights (coalesced inner-loop access: lane = out-channel)
__device__ float g_Wep1T[EDGE_DIM * 64];          // [j][h]
__device__ float g_WaggT[192 * C_N];              // [j][c]
__device__ float g_Wc0T[LOOP_IN * 3 * 64];        // [(ic*3+k)][oc]
__device__ float g_Wc1T[64 * 3 * 64];
__device__ float g_Wc2T[64 * 3 * 64];

// ---------------- prep: weight transposes + coord half of edge_x ----------
__global__ void prep_kernel(const float* __restrict__ W_ep1,
                            const float* __restrict__ W_agg,
                            const float* __restrict__ Wc0,
                            const float* __restrict__ Wc1,
                            const float* __restrict__ Wc2,
                            const float* __restrict__ coord_x) {
    int tid = blockIdx.x * blockDim.x + threadIdx.x;
    int stride = gridDim.x * blockDim.x;
    for (int i = tid; i < EDGE_DIM * 64; i += stride) {
        int j = i >> 6, h = i & 63;
        g_Wep1T[i] = W_ep1[h * EDGE_DIM + j];
    }
    for (int i = tid; i < 192 * C_N; i += stride) {
        int j = i / C_N, c = i % C_N;
        g_WaggT[i] = W_agg[c * 192 + j];
    }
    for (int i = tid; i < LOOP_IN * 3 * 64; i += stride) {
        int ick = i >> 6, oc = i & 63;
        g_Wc0T[i] = Wc0[oc * (LOOP_IN * 3) + ick];
    }
    for (int i = tid; i < 64 * 3 * 64; i += stride) {
        int ick = i >> 6, oc = i & 63;
        g_Wc1T[i] = Wc1[oc * 192 + ick];
        g_Wc2T[i] = Wc2[oc * 192 + ick];
    }
    for (int i = tid; i < E_N * C_N; i += stride) {
        int e = i / C_N, c = i % C_N;
        g_edge_x[e * EDGE_DIM + C_N + c] = coord_x[i];
    }
}

// ---------------- global max pool: warp per (e,c) row --------------------
__global__ void __launch_bounds__(128, 16) pool_kernel(const float* __restrict__ image_x) {
    int gwarp = (blockIdx.x * blockDim.x + threadIdx.x) >> 5;   // 0..32767
    int lane = threadIdx.x & 31;
    const float4* row = (const float4*)(image_x + (size_t)gwarp * HW);
    float m = -FLT_MAX;
    // 784 float4 per row; 24 full rounds of 32 + tail of 16
    #pragma unroll 8
    for (int i = lane; i < 768; i += 32) {
        float4 v = row[i];
        m = fmaxf(m, fmaxf(fmaxf(v.x, v.y), fmaxf(v.z, v.w)));
    }
    if (lane < 16) {
        float4 v = row[768 + lane];
        m = fmaxf(m, fmaxf(fmaxf(v.x, v.y), fmaxf(v.z, v.w)));
    }
    #pragma unroll
    for (int o = 16; o; o >>= 1) m = fmaxf(m, __shfl_xor_sync(0xFFFFFFFFu, m, o));
    if (lane == 0) {
        int e = gwarp / C_N, c = gwarp % C_N;
        g_edge_x[e * EDGE_DIM + c] = m;
    }
}

// ---------------- fused: edge confidence MLP + corner scatter-mean -------
// blocks [0, E_N): edgeconf for edge e = blockIdx.x (256 thr = 64 h x 4 j-chunks)
// blocks [E_N, E_N+NC): cornerfeat for corner c = blockIdx.x - E_N (compacted gather)
__global__ void edge_corner_kernel(const int* __restrict__ pairs,
                                   const float* __restrict__ b_ep1,
                                   const float* __restrict__ W_ep2,
                                   const float* __restrict__ b_ep2,
                                   float* out_conf) {       // nullable
    __shared__ float s_f[256];     // edgeconf: input row / cornerfeat: unused
    __shared__ float s_part[256];
    __shared__ float sh[64];
    __shared__ int   s_list[NP];   // cornerfeat: packed (p<<10)|edge
    __shared__ int   s_n;
    int bid = blockIdx.x, t = threadIdx.x;

    if (bid < E_N) {
        if (!out_conf) return;     // edge_conf is output-only, nothing downstream
        s_f[t] = g_edge_x[bid * EDGE_DIM + t];
        __syncthreads();
        int h = t & 63, jc = t >> 6;
        float acc = 0.f;
        const float* w = g_Wep1T + (jc * 64) * 64;
        const float* x = s_f + jc * 64;
        #pragma unroll 8
        for (int j = 0; j < 64; j++) acc += w[j * 64 + h] * x[j];
        s_part[t] = acc;
        __syncthreads();
        if (t < 64) {
            float a = s_part[t] + s_part[64 + t] + s_part[128 + t] + s_part[192 + t] + b_ep1[t];
            sh[t] = fmaxf(a, 0.f) * W_ep2[t];
        }
        __syncthreads();
        if (t < 32) {
            float v = sh[t] + sh[t + 32];
            #pragma unroll
            for (int o = 16; o; o >>= 1) v += __shfl_xor_sync(0xFFFFFFFFu, v, o);
            if (t == 0) out_conf[bid] = 1.f / (1.f + expf(-(v + b_ep2[0])));
        }
    } else {
        int c = bid - E_N;
        if (t == 0) s_n = 0;
        __syncthreads();
        // cooperative scan of all pairs; compact matches (packed with index for sort)
        for (int p = t; p < NP; p += 256) {
            if (pairs[2 * p] == c) {
                int idx = atomicAdd(&s_n, 1);
                s_list[idx] = (p << 10) | pairs[2 * p + 1];
            }
        }
        __syncthreads();
        int n = s_n;
        // sort by pair index (deterministic accumulation order); n is tiny (~2.6 avg)
        if (t == 0 && n > 1) {
            for (int i = 1; i < n; i++) {
                int v = s_list[i], j = i - 1;
                while (j >= 0 && s_list[j] > v) { s_list[j + 1] = s_list[j]; j--; }
                s_list[j + 1] = v;
            }
        }
        __syncthreads();
        float acc = 0.f;
        for (int i = 0; i < n; i++)
            acc += g_edge_x[(s_list[i] & 1023) * EDGE_DIM + t];
        g_corner_feat[c * EDGE_DIM + t] = acc / fmaxf((float)n, 1.f);
    }
}

// ---------------- loop encoder: block per loop ---------------------------
// threads: 256 = 64 oc x 4 ic-chunks; each thread accumulates ALL 8 positions
__global__ void loopenc_kernel(const int* __restrict__ loops,
                               const float* __restrict__ corners_xy,
                               const float* __restrict__ bc0,
                               const float* __restrict__ bc1,
                               const float* __restrict__ bc2,
                               const float* __restrict__ Wl1,
                               const float* __restrict__ bl1,
                               const float* __restrict__ Wl2,
                               const float* __restrict__ bl2,
                               float* out_loopconf) {       // nullable
    __shared__ float s_a[LOOP_IN * 10];   // padded length-10 rows
    __shared__ float s_b[64 * 10];
    __shared__ float s_c[64 * 10];
    __shared__ float s_red[4 * 64 * 8];   // per-chunk partials [grp][oc][pos]
    __shared__ float s_lf[64];
    __shared__ int   s_cid[LL];
    int nl = blockIdx.x, t = threadIdx.x;
    if (t < LL) s_cid[t] = loops[nl * LL + t];
    __syncthreads();
    // build padded input [258][10]: pos 0 = x[1], pos 1..8 = x[0..7], pos 9 = x[6]
    for (int i = t; i < LOOP_IN * LL; i += 256) {
        int l = i / LOOP_IN, ch = i % LOOP_IN;
        int cid = s_cid[l];
        float v = (ch < EDGE_DIM) ? g_corner_feat[cid * EDGE_DIM + ch]
                                  : corners_xy[cid * 2 + (ch - EDGE_DIM)];
        s_a[ch * 10 + l + 1] = v;
    }
    __syncthreads();
    for (int ch = t; ch < LOOP_IN; ch += 256) {
        s_a[ch * 10]     = s_a[ch * 10 + 2];
        s_a[ch * 10 + 9] = s_a[ch * 10 + 7];
    }
    __syncthreads();

    int oc = t & 63, grp = t >> 6;

    // ---- conv0: 258 -> 64 (ic chunks of 65/65/65/63) ----
    {
        float a[8] = {0,0,0,0,0,0,0,0};
        int ic0 = grp * 65, ic1 = (grp == 3) ? LOOP_IN : ic0 + 65;
        for (int ic = ic0; ic < ic1; ic++) {
            float r[10];
            #pragma unroll
            for (int q = 0; q < 10; q++) r[q] = s_a[ic * 10 + q];
            #pragma unroll
            for (int k = 0; k < 3; k++) {
                float w = g_Wc0T[(ic * 3 + k) * 64 + oc];
                #pragma unroll
                for (int l = 0; l < 8; l++) a[l] += w * r[l + k];
            }
        }
        #pragma unroll
        for (int l = 0; l < 8; l++) s_red[(grp * 64 + oc) * 8 + l] = a[l];
    }
    __syncthreads();
    for (int idx = t; idx < 512; idx += 256) {
        int o2 = idx >> 3, l = idx & 7;
        float v = s_red[(0 * 64 + o2) * 8 + l] + s_red[(1 * 64 + o2) * 8 + l]
                + s_red[(2 * 64 + o2) * 8 + l] + s_red[(3 * 64 + o2) * 8 + l] + bc0[o2];
        s_b[o2 * 10 + l + 1] = fmaxf(v, 0.f);
    }
    __syncthreads();
    if (t < 64) { s_b[t * 10] = s_b[t * 10 + 2]; s_b[t * 10 + 9] = s_b[t * 10 + 7]; }
    __syncthreads();

    // ---- conv1: 64 -> 64 (ic chunks of 16) ----
    {
        float a[8] = {0,0,0,0,0,0,0,0};
        int ic0 = grp * 16;
        for (int ic = ic0; ic < ic0 + 16; ic++) {
            float r[10];
            #pragma unroll
            for (int q = 0; q < 10; q++) r[q] = s_b[ic * 10 + q];
            #pragma unroll
            for (int k = 0; k < 3; k++) {
                float w = g_Wc1T[(ic * 3 + k) * 64 + oc];
                #pragma unroll
                for (int l = 0; l < 8; l++) a[l] += w * r[l + k];
            }
        }
        #pragma unroll
        for (int l = 0; l < 8; l++) s_red[(grp * 64 + oc) * 8 + l] = a[l];
    }
    __syncthreads();
    for (int idx = t; idx < 512; idx += 256) {
        int o2 = idx >> 3, l = idx & 7;
        float v = s_red[(0 * 64 + o2) * 8 + l] + s_red[(1 * 64 + o2) * 8 + l]
                + s_red[(2 * 64 + o2) * 8 + l] + s_red[(3 * 64 + o2) * 8 + l] + bc1[o2];
        s_c[o2 * 10 + l + 1] = fmaxf(v, 0.f);
    }
    __syncthreads();
    if (t < 64) { s_c[t * 10] = s_c[t * 10 + 2]; s_c[t * 10 + 9] = s_c[t * 10 + 7]; }
    __syncthreads();

    // ---- conv2: 64 -> 64, fused relu + max over positions ----
    {
        float a[8] = {0,0,0,0,0,0,0,0};
        int ic0 = grp * 16;
        for (int ic = ic0; ic < ic0 + 16; ic++) {
            float r[10];
            #pragma unroll
            for (int q = 0; q < 10; q++) r[q] = s_c[ic * 10 + q];
            #pragma unroll
            for (int k = 0; k < 3; k++) {
                float w = g_Wc2T[(ic * 3 + k) * 64 + oc];
                #pragma unroll
                for (int l = 0; l < 8; l++) a[l] += w * r[l + k];
            }
        }
        #pragma unroll
        for (int l = 0; l < 8; l++) s_red[(grp * 64 + oc) * 8 + l] = a[l];
    }
    __syncthreads();
    if (t < 64) {
        float m = -FLT_MAX;
        #pragma unroll
        for (int l = 0; l < 8; l++) {
            float v = s_red[(0 * 64 + t) * 8 + l] + s_red[(1 * 64 + t) * 8 + l]
                    + s_red[(2 * 64 + t) * 8 + l] + s_red[(3 * 64 + t) * 8 + l] + bc2[t];
            m = fmaxf(m, v);
        }
        float lf = fmaxf(m, 0.f);
        g_loop_feat[nl * 64 + t] = lf;
        s_lf[t] = lf;
    }
    __syncthreads();
    // loop confidence MLP: 64 -> 32 -> 1 (warp 0)
    if (t < 32) {
        float h = bl1[t];
        #pragma unroll 8
        for (int j = 0; j < 64; j++) h += Wl1[t * 64 + j] * s_lf[j];
        float v = fmaxf(h, 0.f) * Wl2[t];
        #pragma unroll
        for (int o = 16; o; o >>= 1) v += __shfl_xor_sync(0xFFFFFFFFu, v, o);
        if (t == 0) {
            float conf = 1.f / (1.f + expf(-(v + bl2[0])));
            g_loop_conf[nl] = conf;
            if (out_loopconf) out_loopconf[nl] = conf;
        }
    }
}

// ---------------- loop-edge incidence + coord_features: block per edge ---
__global__ void loopedge_kernel(const int* __restrict__ edge_corner,
                                const int* __restrict__ loops,
                                float* out_le) {            // nullable
    __shared__ int   s_loops[NL * LL];
    __shared__ float s_lw[NL];
    int e = blockIdx.x, t = threadIdx.x;   // 64 threads
    for (int i = t; i < NL * LL; i += 64) s_loops[i] = loops[i];
    int a = edge_corner[2 * e], b = edge_corner[2 * e + 1];
    __syncthreads();
    {
        int nl = t;
        const int* c = s_loops + nl * LL;
        bool hit = false;
        #pragma unroll
        for (int l = 0; l < LL; l++) {
            int cl = c[l];
            int cp = c[(l + LL - 1) & 7];
            int cn = c[(l + 1) & 7];
            if (a == cl && (b == cp || b == cn)) hit = true;
        }
        float le = hit ? 1.f : 0.f;
        if (out_le) out_le[nl * E_N + e] = le;
        s_lw[nl] = le * g_loop_conf[nl];
    }
    __syncthreads();
    // t = feature index; loop_feat column read is coalesced across lanes
    float num = 0.f, den = 0.f;
    #pragma unroll 8
    for (int nl = 0; nl < NL; nl++) {
        float w = s_lw[nl];
        den += w;
        num += w * g_loop_feat[nl * 64 + t];
    }
    g_coord_feat[e * 64 + t] = num / fmaxf(den, 1e-4f);
}

// ---------------- final 1x1 conv (no bias) + relu: block per edge --------
// 256 threads = 128 c x 2 j-chunks of 96
__global__ void final_kernel(const float* __restrict__ coord_x,
                             float* __restrict__ out) {
    __shared__ float sx[192];
    __shared__ float s_part[256];
    int e = blockIdx.x, t = threadIdx.x;
    if (t < C_N) sx[t] = coord_x[e * C_N + t];
    else if (t < 192) sx[t] = g_coord_feat[e * 64 + (t - C_N)];
    __syncthreads();
    int c = t & 127, jc = t >> 7;
    float acc = 0.f;
    const float* w = g_WaggT + (jc * 96) * C_N;
    const float* x = sx + jc * 96;
    #pragma unroll 8
    for (int j = 0; j < 96; j++) acc += w[j * C_N + c] * x[j];
    s_part[t] = acc;
    __syncthreads();
    if (t < C_N) out[e * C_N + t] = fmaxf(s_part[t] + s_part[128 + t], 0.f);
}

// ---------------- launch ---------------------------------------------------
extern "C" void kernel_launch(void* const* d_in, const int* in_sizes, int n_in,
                              void* d_out, int out_size) {
    const float* image_x     = (const float*)d_in[0];
    const float* coord_x     = (const float*)d_in[1];
    const float* corners     = (const float*)d_in[2];
    const int*   cep         = (const int*)  d_in[3];
    const int*   edge_corner = (const int*)  d_in[4];
    const int*   loops       = (const int*)  d_in[5];
    const float* W_ep1 = (const float*)d_in[6];
    const float* b_ep1 = (const float*)d_in[7];
    const float* W_ep2 = (const float*)d_in[8];
    const float* b_ep2 = (const float*)d_in[9];
    const float* Wc0   = (const float*)d_in[10];
    const float* bc0   = (const float*)d_in[11];
    const float* Wc1   = (const float*)d_in[12];
    const float* bc1   = (const float*)d_in[13];
    const float* Wc2   = (const float*)d_in[14];
    const float* bc2   = (const float*)d_in[15];
    const float* Wl1   = (const float*)d_in[16];
    const float* bl1   = (const float*)d_in[17];
    const float* Wl2   = (const float*)d_in[18];
    const float* bl2   = (const float*)d_in[19];
    const float* W_agg = (const float*)d_in[20];

    float* out = (float*)d_out;
    float* p_econf = nullptr;
    float* p_lconf = nullptr;
    float* p_le    = nullptr;
    if (out_size >= OUT_FULL_SIZE) {
        p_econf = out + E_N * C_N;
        p_lconf = p_econf + E_N;
        p_le    = p_lconf + NL;
    }

    prep_kernel<<<64, 256>>>(W_ep1, W_agg, Wc0, Wc1, Wc2, coord_x);
    pool_kernel<<<8192, 128>>>(image_x);
    edge_corner_kernel<<<E_N + NC, 256>>>(cep, b_ep1, W_ep2, b_ep2, p_econf);
    loopenc_kernel<<<NL, 256>>>(loops, corners, bc0, bc1, bc2,
                                Wl1, bl1, Wl2, bl2, p_lconf);
    loopedge_kernel<<<E_N, 64>>>(edge_corner, loops, p_le);
    final_kernel<<<E_N, 256>>>(coord_x, out);
}

// round 11
// speedup vs baseline: 1.7467x; 1.2747x over previous
#include <cuda_runtime.h>
#include <math.h>
#include <float.h>

// Problem dims
#define E_N      256
#define C_N      128
#define HW       3136          // 56*56
#define NC       200
#define NP       512
#define NL       64
#define LL       8
#define EDGE_DIM 256           // 2*C
#define LOOP_IN  258
#define FEAT     64

#define OUT_FULL_SIZE 49472

// ---------------- device scratch ----------------
__device__ float g_edge_x[E_N * EDGE_DIM];
__device__ float g_corner_feat[NC * EDGE_DIM];
__device__ float g_loop_feat[NL * FEAT];
__device__ float g_loop_conf[NL];
// transposed weights (lane = out-channel)
__device__ __align__(16) float g_Wep1T[EDGE_DIM * 64];
__device__ __align__(16) float g_WaggT[192 * C_N];
__device__ __align__(16) float g_Wc0T[LOOP_IN * 3 * 64];
__device__ __align__(16) float g_Wc1T[64 * 3 * 64];
__device__ __align__(16) float g_Wc2T[64 * 3 * 64];

// ---------------- fused pool (blocks 0..8191) + prep (blocks 8192..8255) --
__global__ void __launch_bounds__(128, 16) pool_prep_kernel(
        const float* __restrict__ image_x,
        const float* __restrict__ W_ep1,
        const float* __restrict__ W_agg,
        const float* __restrict__ Wc0,
        const float* __restrict__ Wc1,
        const float* __restrict__ Wc2,
        const float* __restrict__ coord_x) {
    if (blockIdx.x < 8192) {
        int gwarp = (blockIdx.x * 128 + threadIdx.x) >> 5;   // 0..32767
        int lane = threadIdx.x & 31;
        const float4* row = (const float4*)(image_x + (size_t)gwarp * HW);
        float m = -FLT_MAX;
        #pragma unroll 8
        for (int i = lane; i < 768; i += 32) {
            float4 v = row[i];
            m = fmaxf(m, fmaxf(fmaxf(v.x, v.y), fmaxf(v.z, v.w)));
        }
        if (lane < 16) {
            float4 v = row[768 + lane];
            m = fmaxf(m, fmaxf(fmaxf(v.x, v.y), fmaxf(v.z, v.w)));
        }
        #pragma unroll
        for (int o = 16; o; o >>= 1) m = fmaxf(m, __shfl_xor_sync(0xFFFFFFFFu, m, o));
        if (lane == 0) {
            int e = gwarp / C_N, c = gwarp % C_N;
            g_edge_x[e * EDGE_DIM + c] = m;
        }
    } else {
        int tid = (blockIdx.x - 8192) * 128 + threadIdx.x;
        const int stride = 64 * 128;
        for (int i = tid; i < EDGE_DIM * 64; i += stride) {
            int j = i >> 6, h = i & 63;
            g_Wep1T[i] = W_ep1[h * EDGE_DIM + j];
        }
        for (int i = tid; i < 192 * C_N; i += stride) {
            int j = i / C_N, c = i % C_N;
            g_WaggT[i] = W_agg[c * 192 + j];
        }
        for (int i = tid; i < LOOP_IN * 3 * 64; i += stride) {
            int ick = i >> 6, oc = i & 63;
            g_Wc0T[i] = Wc0[oc * (LOOP_IN * 3) + ick];
        }
        for (int i = tid; i < 64 * 3 * 64; i += stride) {
            int ick = i >> 6, oc = i & 63;
            g_Wc1T[i] = Wc1[oc * 192 + ick];
            g_Wc2T[i] = Wc2[oc * 192 + ick];
        }
        for (int i = tid; i < E_N * C_N; i += stride) {
            int e = i / C_N, c = i % C_N;
            g_edge_x[e * EDGE_DIM + C_N + c] = coord_x[i];
        }
    }
}

// ---------------- fused: edge confidence MLP + corner scatter-mean -------
__global__ void edge_corner_kernel(const int* __restrict__ pairs,
                                   const float* __restrict__ b_ep1,
                                   const float* __restrict__ W_ep2,
                                   const float* __restrict__ b_ep2,
                                   float* out_conf) {       // nullable
    __shared__ float s_f[256];
    __shared__ float s_part[256];
    __shared__ float sh[64];
    __shared__ int   s_list[NP];
    __shared__ int   s_n;
    int bid = blockIdx.x, t = threadIdx.x;

    if (bid < E_N) {
        if (!out_conf) return;
        s_f[t] = g_edge_x[bid * EDGE_DIM + t];
        __syncthreads();
        int h = t & 63, jc = t >> 6;
        float acc = 0.f;
        const float* w = g_Wep1T + (jc * 64) * 64;
        const float* x = s_f + jc * 64;
        #pragma unroll 8
        for (int j = 0; j < 64; j++) acc += w[j * 64 + h] * x[j];
        s_part[t] = acc;
        __syncthreads();
        if (t < 64) {
            float a = s_part[t] + s_part[64 + t] + s_part[128 + t] + s_part[192 + t] + b_ep1[t];
            sh[t] = fmaxf(a, 0.f) * W_ep2[t];
        }
        __syncthreads();
        if (t < 32) {
            float v = sh[t] + sh[t + 32];
            #pragma unroll
            for (int o = 16; o; o >>= 1) v += __shfl_xor_sync(0xFFFFFFFFu, v, o);
            if (t == 0) out_conf[bid] = 1.f / (1.f + expf(-(v + b_ep2[0])));
        }
    } else {
        int c = bid - E_N;
        if (t == 0) s_n = 0;
        __syncthreads();
        for (int p = t; p < NP; p += 256) {
            if (pairs[2 * p] == c) {
                int idx = atomicAdd(&s_n, 1);
                s_list[idx] = (p << 10) | pairs[2 * p + 1];
            }
        }
        __syncthreads();
        int n = s_n;
        if (t == 0 && n > 1) {
            for (int i = 1; i < n; i++) {
                int v = s_list[i], j = i - 1;
                while (j >= 0 && s_list[j] > v) { s_list[j + 1] = s_list[j]; j--; }
                s_list[j + 1] = v;
            }
        }
        __syncthreads();
        float acc = 0.f;
        for (int i = 0; i < n; i++)
            acc += g_edge_x[(s_list[i] & 1023) * EDGE_DIM + t];
        g_corner_feat[c * EDGE_DIM + t] = acc / fmaxf((float)n, 1.f);
    }
}

// ---------------- loop encoder v3: smem-staged weights -------------------
// 256 threads = 64 oc x 4 ic-chunks; weights tiled into smem (32 ic / tile)
__global__ void __launch_bounds__(256, 2) loopenc_kernel(
                               const int* __restrict__ loops,
                               const float* __restrict__ corners_xy,
                               const float* __restrict__ bc0,
                               const float* __restrict__ bc1,
                               const float* __restrict__ bc2,
                               const float* __restrict__ Wl1,
                               const float* __restrict__ bl1,
                               const float* __restrict__ Wl2,
                               const float* __restrict__ bl2,
                               float* out_loopconf) {       // nullable
    __shared__ float s_a[LOOP_IN * 10];   // input; aliased as s_red after conv reads
    __shared__ float s_b[64 * 10];
    __shared__ float s_c[64 * 10];
    __shared__ float s_w[32 * 3 * 64];    // weight tile (24 KB)
    __shared__ float s_lf[64];
    __shared__ int   s_cid[LL];
    float* s_red = s_a;                    // alias: 2048 <= 2580
    int nl = blockIdx.x, t = threadIdx.x;
    if (t < LL) s_cid[t] = loops[nl * LL + t];
    __syncthreads();
    // padded input [258][10]: pos 0 = x[1], pos 1..8 = x[0..7], pos 9 = x[6]
    for (int i = t; i < LOOP_IN * LL; i += 256) {
        int l = i / LOOP_IN, ch = i % LOOP_IN;
        int cid = s_cid[l];
        float v = (ch < EDGE_DIM) ? g_corner_feat[cid * EDGE_DIM + ch]
                                  : corners_xy[cid * 2 + (ch - EDGE_DIM)];
        s_a[ch * 10 + l + 1] = v;
    }
    __syncthreads();
    for (int ch = t; ch < LOOP_IN; ch += 256) {
        s_a[ch * 10]     = s_a[ch * 10 + 2];
        s_a[ch * 10 + 9] = s_a[ch * 10 + 7];
    }

    int oc = t & 63, grp = t >> 6;

    // ---- conv0: 258 -> 64, tiles of 32 ic ----
    float a[8] = {0,0,0,0,0,0,0,0};
    for (int ic0 = 0; ic0 < LOOP_IN; ic0 += 32) {
        int tsz = (LOOP_IN - ic0 < 32) ? (LOOP_IN - ic0) : 32;
        __syncthreads();   // prior tile readers done / input build done
        for (int i = t; i < tsz * 48; i += 256)
            ((float4*)s_w)[i] = ((const float4*)g_Wc0T)[ic0 * 48 + i];
        __syncthreads();
        for (int il = grp; il < tsz; il += 4) {
            int ic = ic0 + il;
            float r[10];
            #pragma unroll
            for (int q = 0; q < 10; q++) r[q] = s_a[ic * 10 + q];
            #pragma unroll
            for (int k = 0; k < 3; k++) {
                float w = s_w[(il * 3 + k) * 64 + oc];
                #pragma unroll
                for (int l = 0; l < 8; l++) a[l] += w * r[l + k];
            }
        }
    }
    __syncthreads();   // all s_a reads done before aliased s_red writes
    #pragma unroll
    for (int l = 0; l < 8; l++) s_red[(grp * 64 + oc) * 8 + l] = a[l];
    __syncthreads();
    for (int idx = t; idx < 512; idx += 256) {
        int o2 = idx >> 3, l = idx & 7;
        float v = s_red[(0 * 64 + o2) * 8 + l] + s_red[(1 * 64 + o2) * 8 + l]
                + s_red[(2 * 64 + o2) * 8 + l] + s_red[(3 * 64 + o2) * 8 + l] + bc0[o2];
        s_b[o2 * 10 + l + 1] = fmaxf(v, 0.f);
    }
    __syncthreads();
    if (t < 64) { s_b[t * 10] = s_b[t * 10 + 2]; s_b[t * 10 + 9] = s_b[t * 10 + 7]; }

    // ---- conv1: 64 -> 64, 2 tiles ----
    #pragma unroll
    for (int l = 0; l < 8; l++) a[l] = 0.f;
    for (int ic0 = 0; ic0 < 64; ic0 += 32) {
        __syncthreads();
        for (int i = t; i < 32 * 48; i += 256)
            ((float4*)s_w)[i] = ((const float4*)g_Wc1T)[ic0 * 48 + i];
        __syncthreads();
        for (int il = grp; il < 32; il += 4) {
            int ic = ic0 + il;
            float r[10];
            #pragma unroll
            for (int q = 0; q < 10; q++) r[q] = s_b[ic * 10 + q];
            #pragma unroll
            for (int k = 0; k < 3; k++) {
                float w = s_w[(il * 3 + k) * 64 + oc];
                #pragma unroll
                for (int l = 0; l < 8; l++) a[l] += w * r[l + k];
            }
        }
    }
    __syncthreads();
    #pragma unroll
    for (int l = 0; l < 8; l++) s_red[(grp * 64 + oc) * 8 + l] = a[l];
    __syncthreads();
    for (int idx = t; idx < 512; idx += 256) {
        int o2 = idx >> 3, l = idx & 7;
        float v = s_red[(0 * 64 + o2) * 8 + l] + s_red[(1 * 64 + o2) * 8 + l]
                + s_red[(2 * 64 + o2) * 8 + l] + s_red[(3 * 64 + o2) * 8 + l] + bc1[o2];
        s_c[o2 * 10 + l + 1] = fmaxf(v, 0.f);
    }
    __syncthreads();
    if (t < 64) { s_c[t * 10] = s_c[t * 10 + 2]; s_c[t * 10 + 9] = s_c[t * 10 + 7]; }

    // ---- conv2: 64 -> 64, fused relu + max over positions ----
    #pragma unroll
    for (int l = 0; l < 8; l++) a[l] = 0.f;
    for (int ic0 = 0; ic0 < 64; ic0 += 32) {
        __syncthreads();
        for (int i = t; i < 32 * 48; i += 256)
            ((float4*)s_w)[i] = ((const float4*)g_Wc2T)[ic0 * 48 + i];
        __syncthreads();
        for (int il = grp; il < 32; il += 4) {
            int ic = ic0 + il;
            float r[10];
            #pragma unroll
            for (int q = 0; q < 10; q++) r[q] = s_c[ic * 10 + q];
            #pragma unroll
            for (int k = 0; k < 3; k++) {
                float w = s_w[(il * 3 + k) * 64 + oc];
                #pragma unroll
                for (int l = 0; l < 8; l++) a[l] += w * r[l + k];
            }
        }
    }
    __syncthreads();
    #pragma unroll
    for (int l = 0; l < 8; l++) s_red[(grp * 64 + oc) * 8 + l] = a[l];
    __syncthreads();
    if (t < 64) {
        float m = -FLT_MAX;
        #pragma unroll
        for (int l = 0; l < 8; l++) {
            float v = s_red[(0 * 64 + t) * 8 + l] + s_red[(1 * 64 + t) * 8 + l]
                    + s_red[(2 * 64 + t) * 8 + l] + s_red[(3 * 64 + t) * 8 + l] + bc2[t];
            m = fmaxf(m, v);
        }
        float lf = fmaxf(m, 0.f);
        g_loop_feat[nl * 64 + t] = lf;
        s_lf[t] = lf;
    }
    __syncthreads();
    if (t < 32) {
        float h = bl1[t];
        #pragma unroll 8
        for (int j = 0; j < 64; j++) h += Wl1[t * 64 + j] * s_lf[j];
        float v = fmaxf(h, 0.f) * Wl2[t];
        #pragma unroll
        for (int o = 16; o; o >>= 1) v += __shfl_xor_sync(0xFFFFFFFFu, v, o);
        if (t == 0) {
            float conf = 1.f / (1.f + expf(-(v + bl2[0])));
            g_loop_conf[nl] = conf;
            if (out_loopconf) out_loopconf[nl] = conf;
        }
    }
}

// ---------------- fused loop-edge incidence + coord_feat + final conv ----
// block per edge, 256 threads
__global__ void loopedge_final_kernel(const int* __restrict__ edge_corner,
                                      const int* __restrict__ loops,
                                      const float* __restrict__ coord_x,
                                      float* __restrict__ out,
                                      float* out_le) {      // nullable
    __shared__ int   s_loops[NL * LL];
    __shared__ float s_lw[NL];
    __shared__ float s_num[256];
    __shared__ float s_den[256];
    __shared__ float sx[192];
    int e = blockIdx.x, t = threadIdx.x;
    for (int i = t; i < NL * LL; i += 256) s_loops[i] = loops[i];
    int a = edge_corner[2 * e], b = edge_corner[2 * e + 1];
    if (t < C_N) sx[t] = coord_x[e * C_N + t];
    __syncthreads();
    if (t < NL) {
        const int* c = s_loops + t * LL;
        bool hit = false;
        #pragma unroll
        for (int l = 0; l < LL; l++) {
            int cl = c[l];
            int cp = c[(l + LL - 1) & 7];
            int cn = c[(l + 1) & 7];
            if (a == cl && (b == cp || b == cn)) hit = true;
        }
        float le = hit ? 1.f : 0.f;
        if (out_le) out_le[t * E_N + e] = le;
        s_lw[t] = le * g_loop_conf[t];
    }
    __syncthreads();
    {
        int f = t & 63, g = t >> 6;
        float num = 0.f, den = 0.f;
        #pragma unroll
        for (int nl = g * 16; nl < g * 16 + 16; nl++) {
            float w = s_lw[nl];
            den += w;
            num += w * g_loop_feat[nl * 64 + f];
        }
        s_num[t] = num; s_den[t] = den;
    }
    __syncthreads();
    if (t < 64) {
        float nn = s_num[t] + s_num[64 + t] + s_num[128 + t] + s_num[192 + t];
        float dd = s_den[t] + s_den[64 + t] + s_den[128 + t] + s_den[192 + t];
        sx[C_N + t] = nn / fmaxf(dd, 1e-4f);
    }
    __syncthreads();
    // final 1x1 conv + relu: 128 c x 2 j-chunks of 96
    int c = t & 127, jc = t >> 7;
    float acc = 0.f;
    const float* w = g_WaggT + (jc * 96) * C_N;
    const float* x = sx + jc * 96;
    #pragma unroll 8
    for (int j = 0; j < 96; j++) acc += w[j * C_N + c] * x[j];
    s_num[t] = acc;
    __syncthreads();
    if (t < C_N) out[e * C_N + t] = fmaxf(s_num[t] + s_num[128 + t], 0.f);
}

// ---------------- launch ---------------------------------------------------
extern "C" void kernel_launch(void* const* d_in, const int* in_sizes, int n_in,
                              void* d_out, int out_size) {
    const float* image_x     = (const float*)d_in[0];
    const float* coord_x     = (const float*)d_in[1];
    const float* corners     = (const float*)d_in[2];
    const int*   cep         = (const int*)  d_in[3];
    const int*   edge_corner = (const int*)  d_in[4];
    const int*   loops       = (const int*)  d_in[5];
    const float* W_ep1 = (const float*)d_in[6];
    const float* b_ep1 = (const float*)d_in[7];
    const float* W_ep2 = (const float*)d_in[8];
    const float* b_ep2 = (const float*)d_in[9];
    const float* Wc0   = (const float*)d_in[10];
    const float* bc0   = (const float*)d_in[11];
    const float* Wc1   = (const float*)d_in[12];
    const float* bc1   = (const float*)d_in[13];
    const float* Wc2   = (const float*)d_in[14];
    const float* bc2   = (const float*)d_in[15];
    const float* Wl1   = (const float*)d_in[16];
    const float* bl1   = (const float*)d_in[17];
    const float* Wl2   = (const float*)d_in[18];
    const float* bl2   = (const float*)d_in[19];
    const float* W_agg = (const float*)d_in[20];

    float* out = (float*)d_out;
    float* p_econf = nullptr;
    float* p_lconf = nullptr;
    float* p_le    = nullptr;
    if (out_size >= OUT_FULL_SIZE) {
        p_econf = out + E_N * C_N;
        p_lconf = p_econf + E_N;
        p_le    = p_lconf + NL;
    }

    pool_prep_kernel<<<8256, 128>>>(image_x, W_ep1, W_agg, Wc0, Wc1, Wc2, coord_x);
    edge_corner_kernel<<<E_N + NC, 256>>>(cep, b_ep1, W_ep2, b_ep2, p_econf);
    loopenc_kernel<<<NL, 256>>>(loops, corners, bc0, bc1, bc2,
                                Wl1, bl1, Wl2, bl2, p_lconf);
    loopedge_final_kernel<<<E_N, 256>>>(edge_corner, loops, coord_x, out, p_le);
}